// round 8
// baseline (speedup 1.0000x reference)
#include <cuda_runtime.h>
#include <cstdint>

// input_ids : [131072] int32    item_codes: [1000000, 8] int32
// centroids : [8, 256, 64] f32  out: [131072, 512] f32
// out[t, m*64:(m+1)*64] = centroids[m, min(codes[ids[t],m],255)]; ids[t]==0 -> 0.
// setup guarantees centroids[:,0,:]==0 -> pad token maps to code 0, branch-free.
//
// g-major schedule (mgroup g owns PQ dims {2g, 2g+1}): per-block centroid read
// working set = 128KB -> L1-resident; centroid reads leave the L2/DRAM path.
// No smem, no syncs: each warp-iteration is one token's 512B slice with a
// flat id -> code -> centroid -> store chain, 8 independent iters (MLP=8).

static constexpr int THREADS       = 256;
static constexpr int TOK_PER_BLOCK = 64;
static constexpr int TOK_PER_WARP  = 8;

__global__ void __launch_bounds__(THREADS)
pq_gflat_kernel(const int* __restrict__ input_ids,
                const int* __restrict__ item_codes,
                const float4* __restrict__ centroids4,   // [8][256][16] float4
                float4* __restrict__ out4,               // [tokens][128] float4
                int n_tokens, int nchunks)
{
    const int g     = blockIdx.x / nchunks;              // mgroup 0..3 (major)
    const int chunk = blockIdx.x - g * nchunks;
    const int base  = chunk * TOK_PER_BLOCK;

    const int lane = threadIdx.x & 31;
    const int w    = threadIdx.x >> 5;
    const int half = lane >> 4;                          // m = 2g+half
    const int e    = lane & 15;                          // float4 slot in 256B row
    const int moff = 2 * g + half;

    const float4* __restrict__ tab = centroids4 + (size_t)moff * 256 * 16;
    const int wbase = base + w * TOK_PER_WARP;

    if (wbase + TOK_PER_WARP <= n_tokens) {
        // fast path: no bounds checks, 8 independent token slices
        #pragma unroll
        for (int i = 0; i < TOK_PER_WARP; i++) {
            const int t  = wbase + i;
            const int id = __ldg(input_ids + t);                 // warp broadcast
            int c = 0;
            if (id != 0)
                c = min(__ldg(item_codes + (size_t)id * 8 + moff), 255);
            const float4 v = __ldg(tab + c * 16 + e);            // L1-resident
            __stcs(out4 + (size_t)t * 128 + g * 32 + lane, v);   // 512B/warp
        }
    } else {
        for (int i = 0; i < TOK_PER_WARP; i++) {
            const int t = wbase + i;
            if (t >= n_tokens) break;
            const int id = __ldg(input_ids + t);
            int c = 0;
            if (id != 0)
                c = min(__ldg(item_codes + (size_t)id * 8 + moff), 255);
            const float4 v = __ldg(tab + c * 16 + e);
            __stcs(out4 + (size_t)t * 128 + g * 32 + lane, v);
        }
    }
}

extern "C" void kernel_launch(void* const* d_in, const int* in_sizes, int n_in,
                              void* d_out, int out_size)
{
    const int*    input_ids  = (const int*)d_in[0];
    const int*    item_codes = (const int*)d_in[1];
    const float4* centroids4 = (const float4*)d_in[2];
    float4*       out4       = (float4*)d_out;

    const int n_tokens = in_sizes[0];                    // 131072
    const int nchunks  = (n_tokens + TOK_PER_BLOCK - 1) / TOK_PER_BLOCK; // 2048

    pq_gflat_kernel<<<4 * nchunks, THREADS>>>(input_ids, item_codes,
                                              centroids4, out4,
                                              n_tokens, nchunks);
}